// round 1
// baseline (speedup 1.0000x reference)
#include <cuda_runtime.h>

#define NSET 16
#define M    256
#define DIN  128
#define H    8
#define D    64
#define E    (H * D)            // 512
#define L    (NSET * NSET * M)  // 65536

// Scratch: projected features h[j][i][m][e], e = head*64 + d.  134 MB.
__device__ float g_h[(size_t)L * E];
// Per-(pair,head) reduced scores (already fully scaled).
__device__ float g_sc[NSET * NSET * H];

// ---------------------------------------------------------------------------
// Kernel 1: projection GEMM  [L x DIN] @ [DIN x E] -> g_h
// 64x64 block tile, 16x16 threads, 4x4 micro-tile, K-tile 16.
// ---------------------------------------------------------------------------
__global__ void proj_kernel(const float* __restrict__ x,
                            const float* __restrict__ W1) {
    __shared__ float As[64][16];
    __shared__ float Bs[16][65];   // +1 pad
    const int t  = threadIdx.x;
    const int tx = t & 15;
    const int ty = t >> 4;
    const int rowBase = blockIdx.x * 64;
    const int colBase = blockIdx.y * 64;

    float acc[4][4];
#pragma unroll
    for (int i = 0; i < 4; i++)
#pragma unroll
        for (int j = 0; j < 4; j++) acc[i][j] = 0.f;

    for (int k0 = 0; k0 < DIN; k0 += 16) {
#pragma unroll
        for (int i = 0; i < 4; i++) {
            int idx = t + i * 256;
            As[idx >> 4][idx & 15] =
                x[(size_t)(rowBase + (idx >> 4)) * DIN + k0 + (idx & 15)];
            Bs[idx >> 6][idx & 63] =
                W1[(size_t)(k0 + (idx >> 6)) * E + colBase + (idx & 63)];
        }
        __syncthreads();
#pragma unroll
        for (int kk = 0; kk < 16; kk++) {
            float a[4], b[4];
#pragma unroll
            for (int i = 0; i < 4; i++) a[i] = As[ty * 4 + i][kk];
#pragma unroll
            for (int j = 0; j < 4; j++) b[j] = Bs[kk][tx * 4 + j];
#pragma unroll
            for (int i = 0; i < 4; i++)
#pragma unroll
                for (int j = 0; j < 4; j++) acc[i][j] += a[i] * b[j];
        }
        __syncthreads();
    }
#pragma unroll
    for (int i = 0; i < 4; i++)
#pragma unroll
        for (int j = 0; j < 4; j++)
            g_h[(size_t)(rowBase + ty * 4 + i) * E + colBase + tx * 4 + j] =
                acc[i][j];
}

// ---------------------------------------------------------------------------
// Kernel 2: per-(pair, head) score GEMM + LeakyReLU + full reduction.
// blockIdx.x = pair p (j = p>>4, i = p&15), blockIdx.y = head.
// A = h[j,i,head]  [256 x 64]   (rows in registers, one row per thread)
// B = h[i,j,head]  [256 x 64]   (broadcast from smem as float4)
// sum_{m,n} leaky(dot(A_m, B_n)) * 1/(8 * nItem[i] * nItem[j])
// ---------------------------------------------------------------------------
__global__ void score_kernel(const float* __restrict__ nItem) {
    extern __shared__ float smem[];
    float* Ash = smem;             // 256*64
    float* Bsh = smem + M * D;     // 256*64

    const int p    = blockIdx.x;
    const int head = blockIdx.y;
    const int j    = p >> 4;
    const int i    = p & 15;
    const int t    = threadIdx.x;  // 256 threads

    const float* Ag = g_h + (size_t)(j * NSET + i) * M * E + head * D;
    const float* Bg = g_h + (size_t)(i * NSET + j) * M * E + head * D;

    for (int idx = t; idx < M * D; idx += 256) {
        int r = idx >> 6, c = idx & 63;
        Ash[idx] = Ag[(size_t)r * E + c];
        Bsh[idx] = Bg[(size_t)r * E + c];
    }
    __syncthreads();

    // Thread t owns output row m = t. A-row into registers.
    float4 av[16];
    const float4* arow = (const float4*)(Ash + t * D);
#pragma unroll
    for (int q = 0; q < 16; q++) av[q] = arow[q];

    float total = 0.f;
    for (int n = 0; n < M; n++) {
        const float4* brow = (const float4*)(Bsh + n * D);
        float s0 = 0.f, s1 = 0.f, s2 = 0.f, s3 = 0.f;
#pragma unroll
        for (int q = 0; q < 16; q++) {
            float4 b  = brow[q];   // warp-broadcast LDS.128
            float4 aa = av[q];
            s0 += aa.x * b.x;
            s1 += aa.y * b.y;
            s2 += aa.z * b.z;
            s3 += aa.w * b.w;
        }
        float s = (s0 + s1) + (s2 + s3);
        total += (s > 0.f) ? s : 0.3f * s;
    }

    // Block reduction (reuse Ash region after sync).
    __syncthreads();
    smem[t] = total;
    __syncthreads();
    for (int ofs = 128; ofs > 0; ofs >>= 1) {
        if (t < ofs) smem[t] += smem[t + ofs];
        __syncthreads();
    }
    if (t == 0) {
        // fold 1/sqrt(D)=1/8 and 1/(nItem[i]*nItem[j]) here (leaky commutes
        // with positive scaling)
        float scale = 1.0f / (8.0f * nItem[i] * nItem[j]);
        g_sc[p * H + head] = smem[0] * scale;
    }
}

// ---------------------------------------------------------------------------
// Kernel 3: out[p] = sum_h g_sc[p][h] * W2[h]   (deterministic, no atomics)
// ---------------------------------------------------------------------------
__global__ void final_kernel(const float* __restrict__ W2,
                             float* __restrict__ out) {
    int p = threadIdx.x;  // 256
    float s = 0.f;
#pragma unroll
    for (int h = 0; h < H; h++) s += g_sc[p * H + h] * W2[h];
    out[p] = s;
}

// ---------------------------------------------------------------------------
extern "C" void kernel_launch(void* const* d_in, const int* in_sizes, int n_in,
                              void* d_out, int out_size) {
    const float* x     = (const float*)d_in[0];
    const float* nItem = (const float*)d_in[1];
    const float* W1    = (const float*)d_in[2];
    const float* W2    = (const float*)d_in[3];
    float* out = (float*)d_out;

    cudaFuncSetAttribute(score_kernel,
                         cudaFuncAttributeMaxDynamicSharedMemorySize,
                         2 * M * D * (int)sizeof(float));

    dim3 pgrid(L / 64, E / 64);            // (1024, 8)
    proj_kernel<<<pgrid, 256>>>(x, W1);

    dim3 sgrid(NSET * NSET, H);            // (256, 8)
    score_kernel<<<sgrid, 256, 2 * M * D * sizeof(float)>>>(nItem);

    final_kernel<<<1, 256>>>(W2, out);
}

// round 6
// speedup vs baseline: 10.2490x; 10.2490x over previous
#include <cuda_runtime.h>
#include <cuda_fp16.h>
#include <cstdint>

// N=16 sets, M=256 items, D_IN=128, H=8, D=64 -> E=512
// out[j,i] = sum_h W2[h] * (sum_{m,n} leaky(h[j,i,h,m,:].h[i,j,h,n,:] / 8)) / (nItem[i]*nItem[j])
// Symmetric in (i,j): 136 unordered pairs computed.
// Tensor path: mma.sync m16n8k16 f16 (baseline ISA, valid on sm_100 target).
// fp16 (not bf16): 10-bit mantissa needed to clear the 1e-3 rel-err gate.

#define NSET 16
#define DIN  128
#define EE   512

// h blobs: 2048 blobs ((j*16+i)*8+head), each 32 KB = 256 rows x 64 fp16 cols,
// 128 B/row, 16B chunks XOR-swizzled by (row&7) -> conflict-free ldmatrix.
__device__ uint4 g_hb4[2048u * 2048u];   // 64 MB
// W1 transposed [e][k] fp16, 256 B rows, chunk-swizzled. 128 KB.
__device__ uint4 g_w1s4[8192];
__device__ float g_sc[2048];

__device__ __forceinline__ uint32_t smem_u32(const void* p) {
    uint32_t a;
    asm("{ .reg .u64 t; cvta.to.shared.u64 t, %1; cvt.u32.u64 %0, t; }" : "=r"(a) : "l"(p));
    return a;
}
__device__ __forceinline__ void ldsm4(uint32_t* r, uint32_t addr) {
    asm volatile("ldmatrix.sync.aligned.m8n8.x4.shared.b16 {%0,%1,%2,%3}, [%4];"
                 : "=r"(r[0]), "=r"(r[1]), "=r"(r[2]), "=r"(r[3]) : "r"(addr));
}
__device__ __forceinline__ void mma_f16(float* c, const uint32_t* a, uint32_t b0, uint32_t b1) {
    asm volatile("mma.sync.aligned.m16n8k16.row.col.f32.f16.f16.f32 "
                 "{%0,%1,%2,%3}, {%4,%5,%6,%7}, {%8,%9}, {%0,%1,%2,%3};"
                 : "+f"(c[0]), "+f"(c[1]), "+f"(c[2]), "+f"(c[3])
                 : "r"(a[0]), "r"(a[1]), "r"(a[2]), "r"(a[3]), "r"(b0), "r"(b1));
}
__device__ __forceinline__ uint32_t pack_h2(float lo, float hi) {
    __half2 h = __floats2half2_rn(lo, hi);
    return *(uint32_t*)&h;
}

// ---------------------------------------------------------------------------
// Kernel 0: W1 [128 x 512] fp32 -> Wt [e][k] fp16, swizzled (256 B rows).
// off(e,k) = e*256 + ((k>>3) ^ (e&7))*16 + (k&7)*2
// ---------------------------------------------------------------------------
__global__ void w1prep_kernel(const float* __restrict__ W1) {
    int idx = blockIdx.x * 256 + threadIdx.x;   // 32768: one half2 each
    int e  = idx >> 6;
    int k  = (idx & 63) * 2;
    uint32_t bv = pack_h2(W1[(size_t)k * EE + e], W1[(size_t)(k + 1) * EE + e]);
    uint32_t off = (uint32_t)e * 256u + (uint32_t)(((k >> 3) ^ (e & 7)) * 16) + (uint32_t)((k & 7) * 2);
    *(uint32_t*)((char*)g_w1s4 + off) = bv;
}

// ---------------------------------------------------------------------------
// Kernel 1: projection h = x @ W1. grid(512, 4), 256 thr (8 warps, 2m x 4n).
// Block tile 128(m) x 128(e), K=128 staged once in smem.
// Warp tile 64 x 32. Epilogue -> fp16 h in score-ready blob layout.
// smem: [A 32K][B 32K]; A region reused as epilogue staging.
// ---------------------------------------------------------------------------
__global__ void __launch_bounds__(256) proj_kernel(const float* __restrict__ x) {
    extern __shared__ char sm[];
    const uint32_t sbA = smem_u32(sm);
    const uint32_t sbB = sbA + 32768u;
    const int t    = threadIdx.x;
    const int wid  = t >> 5;
    const int lane = t & 31;

    const int rowBase = blockIdx.x * 128;
    const int colBase = blockIdx.y * 128;

    // A: x[128 x 128] fp32 -> fp16 swizzled (256 B rows)
    const float2* xb = (const float2*)(x + (size_t)rowBase * DIN);
#pragma unroll
    for (int it = 0; it < 32; it++) {
        int idx = t + it * 256;
        int r = idx >> 6, k = (idx & 63) * 2;
        float2 v = xb[(size_t)r * 64 + (k >> 1)];
        uint32_t off = (uint32_t)(r * 256 + (((k >> 3) ^ (r & 7)) * 16) + ((k & 7) * 2));
        *(uint32_t*)(sm + off) = pack_h2(v.x, v.y);
    }
    // B: linear copy of pre-swizzled Wt rows [colBase .. colBase+127]  (32 KB)
    {
        const uint4* src = g_w1s4 + (size_t)colBase * 16;  // 256 B/row = 16 uint4
        uint4* dst = (uint4*)(sm + 32768);
#pragma unroll
        for (int it = 0; it < 8; it++) dst[t + it * 256] = src[t + it * 256];
    }
    __syncthreads();

    const int warpM = (wid >> 2) * 64;
    const int warpN = (wid & 3) * 32;
    float acc[4][4][4];
#pragma unroll
    for (int mt = 0; mt < 4; mt++)
#pragma unroll
        for (int nt = 0; nt < 4; nt++)
#pragma unroll
            for (int q = 0; q < 4; q++) acc[mt][nt][q] = 0.f;

    const int sel = lane >> 3, l7 = lane & 7;
#pragma unroll
    for (int ks = 0; ks < 8; ks++) {
        const int k0 = ks * 16;
        uint32_t a[4][4], b[2][4];
#pragma unroll
        for (int mt = 0; mt < 4; mt++) {
            int row = warpM + mt * 16 + l7 + (sel & 1) * 8;
            int kc  = k0 + (sel >> 1) * 8;
            ldsm4(a[mt], sbA + (uint32_t)(row * 256 + (((kc >> 3) ^ (row & 7)) * 16)));
        }
#pragma unroll
        for (int np = 0; np < 2; np++) {
            int n  = warpN + np * 16 + (sel >> 1) * 8 + l7;
            int kc = k0 + (sel & 1) * 8;
            ldsm4(b[np], sbB + (uint32_t)(n * 256 + (((kc >> 3) ^ (n & 7)) * 16)));
        }
#pragma unroll
        for (int mt = 0; mt < 4; mt++)
#pragma unroll
            for (int nt = 0; nt < 4; nt++)
                mma_f16(acc[mt][nt], a[mt], b[nt >> 1][(nt & 1) * 2], b[nt >> 1][(nt & 1) * 2 + 1]);
    }
    __syncthreads();

    // Epilogue: stage fp16 tile in blob layout (two 16 KB head-slices) in A region.
    const int r0 = lane >> 2;
    const int c0 = (lane & 3) * 2;
#pragma unroll
    for (int mt = 0; mt < 4; mt++)
#pragma unroll
        for (int nt = 0; nt < 4; nt++) {
            int e_loc = warpN + nt * 8 + c0;
            int hh = e_loc >> 6, d = e_loc & 63;
#pragma unroll
            for (int half = 0; half < 2; half++) {
                int m = warpM + mt * 16 + r0 + half * 8;
                uint32_t off = (uint32_t)(hh * 16384 + m * 128 + (((d >> 3) ^ (m & 7)) * 16) + ((d & 7) * 2));
                *(uint32_t*)(sm + off) = pack_h2(acc[mt][nt][half * 2], acc[mt][nt][half * 2 + 1]);
            }
        }
    __syncthreads();

    // Copy to gmem blobs (16 KB contiguous per head-slice).
    const int pair = blockIdx.x >> 1;
    const int rh   = blockIdx.x & 1;
#pragma unroll
    for (int hh = 0; hh < 2; hh++) {
        int head = blockIdx.y * 2 + hh;
        uint4* dst = g_hb4 + (size_t)(pair * 8 + head) * 2048 + rh * 1024;
        const uint4* src = (const uint4*)(sm + hh * 16384);
#pragma unroll
        for (int it = 0; it < 4; it++) dst[t + it * 256] = src[t + it * 256];
    }
}

// ---------------------------------------------------------------------------
// Kernel 2: score. grid(136, 8): unordered pair {i<=j}, head. 256 thr.
// A = blob(j,i,head)[256x64], B = blob(i,j,head)[256x64], S = A @ B^T.
// Warp w: rows w*32..w*32+31, all 256 cols. Leaky + reduce in registers.
// ---------------------------------------------------------------------------
__global__ void __launch_bounds__(256) score_kernel(const float* __restrict__ nItem) {
    extern __shared__ char sm[];
    __shared__ float red[8];
    const uint32_t sbA = smem_u32(sm);
    const uint32_t sbB = sbA + 32768u;
    const int t    = threadIdx.x;
    const int wid  = t >> 5;
    const int lane = t & 31;

    const int p = blockIdx.x, head = blockIdx.y;
    int j = 0;
    while ((j + 1) * (j + 2) / 2 <= p) j++;
    const int i = p - j * (j + 1) / 2;

    {
        const uint4* As = g_hb4 + (size_t)((j * NSET + i) * 8 + head) * 2048;
        const uint4* Bs = g_hb4 + (size_t)((i * NSET + j) * 8 + head) * 2048;
        uint4* dA = (uint4*)sm;
        uint4* dB = (uint4*)(sm + 32768);
#pragma unroll
        for (int it = 0; it < 8; it++) dA[t + it * 256] = As[t + it * 256];
#pragma unroll
        for (int it = 0; it < 8; it++) dB[t + it * 256] = Bs[t + it * 256];
    }
    __syncthreads();

    const int sel = lane >> 3, l7 = lane & 7;
    float acc = 0.f;

#pragma unroll
    for (int mt = 0; mt < 2; mt++) {
        const int m0 = wid * 32 + mt * 16;
        uint32_t a[4][4];
#pragma unroll
        for (int ks = 0; ks < 4; ks++) {
            int row = m0 + l7 + (sel & 1) * 8;
            int kc  = ks * 16 + (sel >> 1) * 8;
            ldsm4(a[ks], sbA + (uint32_t)(row * 128 + (((kc >> 3) ^ (row & 7)) * 16)));
        }
#pragma unroll
        for (int np = 0; np < 16; np++) {
            const int n0 = np * 16;
            uint32_t b[4][4];
#pragma unroll
            for (int ks = 0; ks < 4; ks++) {
                int n  = n0 + (sel >> 1) * 8 + l7;
                int kc = ks * 16 + (sel & 1) * 8;
                ldsm4(b[ks], sbB + (uint32_t)(n * 128 + (((kc >> 3) ^ (n & 7)) * 16)));
            }
            float c0[4] = {0.f, 0.f, 0.f, 0.f};
            float c1[4] = {0.f, 0.f, 0.f, 0.f};
#pragma unroll
            for (int ks = 0; ks < 4; ks++) {
                mma_f16(c0, a[ks], b[ks][0], b[ks][1]);
                mma_f16(c1, a[ks], b[ks][2], b[ks][3]);
            }
#pragma unroll
            for (int q = 0; q < 4; q++) {
                acc += fmaxf(c0[q], 0.f) + 0.3f * fminf(c0[q], 0.f);
                acc += fmaxf(c1[q], 0.f) + 0.3f * fminf(c1[q], 0.f);
            }
        }
    }

    // warp reduce -> block reduce
#pragma unroll
    for (int o = 16; o > 0; o >>= 1) acc += __shfl_xor_sync(0xFFFFFFFFu, acc, o);
    if (lane == 0) red[wid] = acc;
    __syncthreads();
    if (t == 0) {
        float s = 0.f;
#pragma unroll
        for (int w = 0; w < 8; w++) s += red[w];
        float v = s / (8.f * nItem[i] * nItem[j]);
        g_sc[(j * NSET + i) * 8 + head] = v;
        g_sc[(i * NSET + j) * 8 + head] = v;
    }
}

// ---------------------------------------------------------------------------
__global__ void final_kernel(const float* __restrict__ W2, float* __restrict__ out) {
    int pidx = threadIdx.x;
    float s = 0.f;
#pragma unroll
    for (int h = 0; h < 8; h++) s += g_sc[pidx * 8 + h] * W2[h];
    out[pidx] = s;
}

// ---------------------------------------------------------------------------
extern "C" void kernel_launch(void* const* d_in, const int* in_sizes, int n_in,
                              void* d_out, int out_size) {
    const float* x     = (const float*)d_in[0];
    const float* nItem = (const float*)d_in[1];
    const float* W1    = (const float*)d_in[2];
    const float* W2    = (const float*)d_in[3];
    float* out = (float*)d_out;

    cudaFuncSetAttribute(proj_kernel,  cudaFuncAttributeMaxDynamicSharedMemorySize, 65536);
    cudaFuncSetAttribute(score_kernel, cudaFuncAttributeMaxDynamicSharedMemorySize, 65536);

    w1prep_kernel<<<128, 256>>>(W1);
    proj_kernel<<<dim3(512, 4), 256, 65536>>>(x);
    score_kernel<<<dim3(136, 8), 256, 65536>>>(nItem);
    final_kernel<<<1, 256>>>(W2, out);
}

// round 7
// speedup vs baseline: 10.2851x; 1.0035x over previous
#include <cuda_runtime.h>
#include <cuda_fp16.h>
#include <cstdint>

// N=16 sets, M=256 items, D_IN=128, H=8, D=64 -> E=512
// out[j,i] = sum_h W2[h] * (sum_{m,n} leaky(h[j,i,h,m,:].h[i,j,h,n,:] / 8)) / (nItem[i]*nItem[j])
// Symmetric in (i,j): 136 unordered pairs computed.
// Tensor path: mma.sync m16n8k16 f16 (baseline ISA, valid on sm_100 target).
// fp16 (not bf16): 10-bit mantissa needed to clear the 1e-3 rel-err gate.

#define NSET 16
#define DIN  128
#define EE   512

// h blobs: 2048 blobs ((j*16+i)*8+head), each 32 KB = 256 rows x 64 fp16 cols,
// 128 B/row, 16B chunks XOR-swizzled by (row&7) -> conflict-free ldmatrix.
__device__ uint4 g_hb4[2048u * 2048u];   // 64 MB
// W1 transposed [e][k] fp16, 256 B rows, chunk-swizzled. 128 KB.
__device__ uint4 g_w1s4[8192];
__device__ float g_sc[2048];

__device__ __forceinline__ uint32_t smem_u32(const void* p) {
    uint32_t a;
    asm("{ .reg .u64 t; cvta.to.shared.u64 t, %1; cvt.u32.u64 %0, t; }" : "=r"(a) : "l"(p));
    return a;
}
__device__ __forceinline__ void ldsm4(uint32_t* r, uint32_t addr) {
    asm volatile("ldmatrix.sync.aligned.m8n8.x4.shared.b16 {%0,%1,%2,%3}, [%4];"
                 : "=r"(r[0]), "=r"(r[1]), "=r"(r[2]), "=r"(r[3]) : "r"(addr));
}
__device__ __forceinline__ void mma_f16(float* c, const uint32_t* a, uint32_t b0, uint32_t b1) {
    asm volatile("mma.sync.aligned.m16n8k16.row.col.f32.f16.f16.f32 "
                 "{%0,%1,%2,%3}, {%4,%5,%6,%7}, {%8,%9}, {%0,%1,%2,%3};"
                 : "+f"(c[0]), "+f"(c[1]), "+f"(c[2]), "+f"(c[3])
                 : "r"(a[0]), "r"(a[1]), "r"(a[2]), "r"(a[3]), "r"(b0), "r"(b1));
}
__device__ __forceinline__ uint32_t pack_h2(float lo, float hi) {
    __half2 h = __floats2half2_rn(lo, hi);
    return *(uint32_t*)&h;
}

// ---------------------------------------------------------------------------
// Kernel 0: W1 [128 x 512] fp32 -> Wt [e][k] fp16, swizzled (256 B rows).
// off(e,k) = e*256 + ((k>>3) ^ (e&7))*16 + (k&7)*2
// ---------------------------------------------------------------------------
__global__ void w1prep_kernel(const float* __restrict__ W1) {
    int idx = blockIdx.x * 256 + threadIdx.x;   // 32768: one half2 each
    int e  = idx >> 6;
    int k  = (idx & 63) * 2;
    uint32_t bv = pack_h2(W1[(size_t)k * EE + e], W1[(size_t)(k + 1) * EE + e]);
    uint32_t off = (uint32_t)e * 256u + (uint32_t)(((k >> 3) ^ (e & 7)) * 16) + (uint32_t)((k & 7) * 2);
    *(uint32_t*)((char*)g_w1s4 + off) = bv;
}

// ---------------------------------------------------------------------------
// Kernel 1: projection h = x @ W1. grid(512, 4), 256 thr (8 warps, 2m x 4n).
// Block tile 128(m) x 128(e), K=128 staged once in smem.
// Warp tile 64 x 32. Epilogue -> fp16 h in score-ready blob layout.
// smem: [A 32K][B 32K]; A region reused as epilogue staging.
// ---------------------------------------------------------------------------
__global__ void __launch_bounds__(256) proj_kernel(const float* __restrict__ x) {
    extern __shared__ char sm[];
    const uint32_t sbA = smem_u32(sm);
    const uint32_t sbB = sbA + 32768u;
    const int t    = threadIdx.x;
    const int wid  = t >> 5;
    const int lane = t & 31;

    const int rowBase = blockIdx.x * 128;
    const int colBase = blockIdx.y * 128;

    // A: x[128 x 128] fp32 -> fp16 swizzled (256 B rows)
    const float2* xb = (const float2*)(x + (size_t)rowBase * DIN);
#pragma unroll
    for (int it = 0; it < 32; it++) {
        int idx = t + it * 256;
        int r = idx >> 6, k = (idx & 63) * 2;
        float2 v = xb[(size_t)r * 64 + (k >> 1)];
        uint32_t off = (uint32_t)(r * 256 + (((k >> 3) ^ (r & 7)) * 16) + ((k & 7) * 2));
        *(uint32_t*)(sm + off) = pack_h2(v.x, v.y);
    }
    // B: linear copy of pre-swizzled Wt rows [colBase .. colBase+127]  (32 KB)
    {
        const uint4* src = g_w1s4 + (size_t)colBase * 16;  // 256 B/row = 16 uint4
        uint4* dst = (uint4*)(sm + 32768);
#pragma unroll
        for (int it = 0; it < 8; it++) dst[t + it * 256] = src[t + it * 256];
    }
    __syncthreads();

    const int warpM = (wid >> 2) * 64;
    const int warpN = (wid & 3) * 32;
    float acc[4][4][4];
#pragma unroll
    for (int mt = 0; mt < 4; mt++)
#pragma unroll
        for (int nt = 0; nt < 4; nt++)
#pragma unroll
            for (int q = 0; q < 4; q++) acc[mt][nt][q] = 0.f;

    const int sel = lane >> 3, l7 = lane & 7;
#pragma unroll
    for (int ks = 0; ks < 8; ks++) {
        const int k0 = ks * 16;
        uint32_t a[4][4], b[2][4];
#pragma unroll
        for (int mt = 0; mt < 4; mt++) {
            int row = warpM + mt * 16 + l7 + (sel & 1) * 8;
            int kc  = k0 + (sel >> 1) * 8;
            ldsm4(a[mt], sbA + (uint32_t)(row * 256 + (((kc >> 3) ^ (row & 7)) * 16)));
        }
#pragma unroll
        for (int np = 0; np < 2; np++) {
            int n  = warpN + np * 16 + (sel >> 1) * 8 + l7;
            int kc = k0 + (sel & 1) * 8;
            ldsm4(b[np], sbB + (uint32_t)(n * 256 + (((kc >> 3) ^ (n & 7)) * 16)));
        }
#pragma unroll
        for (int mt = 0; mt < 4; mt++)
#pragma unroll
            for (int nt = 0; nt < 4; nt++)
                mma_f16(acc[mt][nt], a[mt], b[nt >> 1][(nt & 1) * 2], b[nt >> 1][(nt & 1) * 2 + 1]);
    }
    __syncthreads();

    // Epilogue: stage fp16 tile in blob layout (two 16 KB head-slices) in A region.
    const int r0 = lane >> 2;
    const int c0 = (lane & 3) * 2;
#pragma unroll
    for (int mt = 0; mt < 4; mt++)
#pragma unroll
        for (int nt = 0; nt < 4; nt++) {
            int e_loc = warpN + nt * 8 + c0;
            int hh = e_loc >> 6, d = e_loc & 63;
#pragma unroll
            for (int half = 0; half < 2; half++) {
                int m = warpM + mt * 16 + r0 + half * 8;
                uint32_t off = (uint32_t)(hh * 16384 + m * 128 + (((d >> 3) ^ (m & 7)) * 16) + ((d & 7) * 2));
                *(uint32_t*)(sm + off) = pack_h2(acc[mt][nt][half * 2], acc[mt][nt][half * 2 + 1]);
            }
        }
    __syncthreads();

    // Copy to gmem blobs (16 KB contiguous per head-slice).
    const int pair = blockIdx.x >> 1;
    const int rh   = blockIdx.x & 1;
#pragma unroll
    for (int hh = 0; hh < 2; hh++) {
        int head = blockIdx.y * 2 + hh;
        uint4* dst = g_hb4 + (size_t)(pair * 8 + head) * 2048 + rh * 1024;
        const uint4* src = (const uint4*)(sm + hh * 16384);
#pragma unroll
        for (int it = 0; it < 4; it++) dst[t + it * 256] = src[t + it * 256];
    }
}

// ---------------------------------------------------------------------------
// Kernel 2: score. grid(136, 8): unordered pair {i<=j}, head. 256 thr.
// A = blob(j,i,head)[256x64], B = blob(i,j,head)[256x64], S = A @ B^T.
// Warp w: rows w*32..w*32+31, all 256 cols. Leaky + reduce in registers.
// ---------------------------------------------------------------------------
__global__ void __launch_bounds__(256) score_kernel(const float* __restrict__ nItem) {
    extern __shared__ char sm[];
    __shared__ float red[8];
    const uint32_t sbA = smem_u32(sm);
    const uint32_t sbB = sbA + 32768u;
    const int t    = threadIdx.x;
    const int wid  = t >> 5;
    const int lane = t & 31;

    const int p = blockIdx.x, head = blockIdx.y;
    int j = 0;
    while ((j + 1) * (j + 2) / 2 <= p) j++;
    const int i = p - j * (j + 1) / 2;

    {
        const uint4* As = g_hb4 + (size_t)((j * NSET + i) * 8 + head) * 2048;
        const uint4* Bs = g_hb4 + (size_t)((i * NSET + j) * 8 + head) * 2048;
        uint4* dA = (uint4*)sm;
        uint4* dB = (uint4*)(sm + 32768);
#pragma unroll
        for (int it = 0; it < 8; it++) dA[t + it * 256] = As[t + it * 256];
#pragma unroll
        for (int it = 0; it < 8; it++) dB[t + it * 256] = Bs[t + it * 256];
    }
    __syncthreads();

    const int sel = lane >> 3, l7 = lane & 7;
    float acc = 0.f;

#pragma unroll
    for (int mt = 0; mt < 2; mt++) {
        const int m0 = wid * 32 + mt * 16;
        uint32_t a[4][4];
#pragma unroll
        for (int ks = 0; ks < 4; ks++) {
            int row = m0 + l7 + (sel & 1) * 8;
            int kc  = ks * 16 + (sel >> 1) * 8;
            ldsm4(a[ks], sbA + (uint32_t)(row * 128 + (((kc >> 3) ^ (row & 7)) * 16)));
        }
#pragma unroll
        for (int np = 0; np < 16; np++) {
            const int n0 = np * 16;
            uint32_t b[4][4];
#pragma unroll
            for (int ks = 0; ks < 4; ks++) {
                int n  = n0 + (sel >> 1) * 8 + l7;
                int kc = ks * 16 + (sel & 1) * 8;
                ldsm4(b[ks], sbB + (uint32_t)(n * 128 + (((kc >> 3) ^ (n & 7)) * 16)));
            }
            float c0[4] = {0.f, 0.f, 0.f, 0.f};
            float c1[4] = {0.f, 0.f, 0.f, 0.f};
#pragma unroll
            for (int ks = 0; ks < 4; ks++) {
                mma_f16(c0, a[ks], b[ks][0], b[ks][1]);
                mma_f16(c1, a[ks], b[ks][2], b[ks][3]);
            }
#pragma unroll
            for (int q = 0; q < 4; q++) {
                acc += fmaxf(c0[q], 0.f) + 0.3f * fminf(c0[q], 0.f);
                acc += fmaxf(c1[q], 0.f) + 0.3f * fminf(c1[q], 0.f);
            }
        }
    }

    // warp reduce -> block reduce
#pragma unroll
    for (int o = 16; o > 0; o >>= 1) acc += __shfl_xor_sync(0xFFFFFFFFu, acc, o);
    if (lane == 0) red[wid] = acc;
    __syncthreads();
    if (t == 0) {
        float s = 0.f;
#pragma unroll
        for (int w = 0; w < 8; w++) s += red[w];
        float v = s / (8.f * nItem[i] * nItem[j]);
        g_sc[(j * NSET + i) * 8 + head] = v;
        g_sc[(i * NSET + j) * 8 + head] = v;
    }
}

// ---------------------------------------------------------------------------
__global__ void final_kernel(const float* __restrict__ W2, float* __restrict__ out) {
    int pidx = threadIdx.x;
    float s = 0.f;
#pragma unroll
    for (int h = 0; h < 8; h++) s += g_sc[pidx * 8 + h] * W2[h];
    out[pidx] = s;
}

// ---------------------------------------------------------------------------
extern "C" void kernel_launch(void* const* d_in, const int* in_sizes, int n_in,
                              void* d_out, int out_size) {
    const float* x     = (const float*)d_in[0];
    const float* nItem = (const float*)d_in[1];
    const float* W1    = (const float*)d_in[2];
    const float* W2    = (const float*)d_in[3];
    float* out = (float*)d_out;

    cudaFuncSetAttribute(proj_kernel,  cudaFuncAttributeMaxDynamicSharedMemorySize, 65536);
    cudaFuncSetAttribute(score_kernel, cudaFuncAttributeMaxDynamicSharedMemorySize, 65536);

    w1prep_kernel<<<128, 256>>>(W1);
    proj_kernel<<<dim3(512, 4), 256, 65536>>>(x);
    score_kernel<<<dim3(136, 8), 256, 65536>>>(nItem);
    final_kernel<<<1, 256>>>(W2, out);
}